// round 14
// baseline (speedup 1.0000x reference)
#include <cuda_runtime.h>
#include <cuda_bf16.h>
#include <math.h>
#include <stdint.h>

#define B      256
#define HDIM   512
#define NENC   60
#define S1     62
#define S2     63
#define NQ     6
#define KDIM   3584
#define L2P    7168

typedef unsigned long long ull;

static __device__ float g_scratch[163936256];

__device__ __forceinline__ ull dup2(float a) {
    ull d; asm("mov.b64 %0, {%1, %1};" : "=l"(d) : "f"(a)); return d;
}
__device__ __forceinline__ void fma2(ull &acc, ull a, ull b) {
    asm("fma.rn.f32x2 %0, %1, %2, %0;" : "+l"(acc) : "l"(a), "l"(b));
}
__device__ __forceinline__ void unpack2(ull v, float &lo, float &hi) {
    asm("mov.b64 {%0, %1}, %2;" : "=f"(lo), "=f"(hi) : "l"(v));
}
__device__ __forceinline__ uint32_t smem_u32(const void* p) {
    uint32_t a;
    asm("{ .reg .u64 t; cvta.to.shared.u64 t, %1; cvt.u32.u64 %0, t; }" : "=r"(a) : "l"(p));
    return a;
}
__device__ __forceinline__ void cp16(uint32_t s, const void* g) {
    asm volatile("cp.async.cg.shared.global [%0], [%1], 16;" :: "r"(s), "l"(g));
}
#define CP_COMMIT() asm volatile("cp.async.commit_group;" ::: "memory")
#define CP_WAIT(n)  asm volatile("cp.async.wait_group %0;" :: "n"(n) : "memory")

__device__ __forceinline__ void ldsm_x4(uint32_t &r0, uint32_t &r1, uint32_t &r2, uint32_t &r3, uint32_t addr) {
    asm volatile("ldmatrix.sync.aligned.m8n8.x4.shared.b16 {%0,%1,%2,%3}, [%4];"
        : "=r"(r0), "=r"(r1), "=r"(r2), "=r"(r3) : "r"(addr));
}
__device__ __forceinline__ void ldsm_x4_t(uint32_t &r0, uint32_t &r1, uint32_t &r2, uint32_t &r3, uint32_t addr) {
    asm volatile("ldmatrix.sync.aligned.m8n8.x4.trans.shared.b16 {%0,%1,%2,%3}, [%4];"
        : "=r"(r0), "=r"(r1), "=r"(r2), "=r"(r3) : "r"(addr));
}
__device__ __forceinline__ void mma16816(float* d, const uint32_t* a, uint32_t b0, uint32_t b1) {
    asm volatile("mma.sync.aligned.m16n8k16.row.col.f32.bf16.bf16.f32 "
        "{%0,%1,%2,%3}, {%4,%5,%6,%7}, {%8,%9}, {%0,%1,%2,%3};"
        : "+f"(d[0]), "+f"(d[1]), "+f"(d[2]), "+f"(d[3])
        : "r"(a[0]), "r"(a[1]), "r"(a[2]), "r"(a[3]), "r"(b0), "r"(b1));
}
__device__ __forceinline__ void imma16832(int* d, const uint32_t* a, uint32_t b0, uint32_t b1) {
    asm volatile("mma.sync.aligned.m16n8k32.row.col.s32.s8.s8.s32 "
        "{%0,%1,%2,%3}, {%4,%5,%6,%7}, {%8,%9}, {%0,%1,%2,%3};"
        : "+r"(d[0]), "+r"(d[1]), "+r"(d[2]), "+r"(d[3])
        : "r"(a[0]), "r"(a[1]), "r"(a[2]), "r"(a[3]), "r"(b0), "r"(b1));
}
__device__ __forceinline__ __nv_bfloat162 split_hi(float v0, float v1, __nv_bfloat162 &lo) {
    __nv_bfloat16 h0 = __float2bfloat16(v0);
    __nv_bfloat16 h1 = __float2bfloat16(v1);
    lo.x = __float2bfloat16(v0 - __bfloat162float(h0));
    lo.y = __float2bfloat16(v1 - __bfloat162float(h1));
    __nv_bfloat162 hi; hi.x = h0; hi.y = h1;
    return hi;
}

// ---- layer-2 weight (split bf16 [n][k]) ----
__global__ void k_build_cw1e(const float* __restrict__ basis, const float* __restrict__ selfW,
                             __nv_bfloat16* __restrict__ WE) {
    int idx = blockIdx.x * 256 + threadIdx.x;
    if (idx >= HDIM * KDIM) return;
    int n = idx / KDIM, k = idx - n * KDIM;
    float w = (k < 3072) ? basis[(size_t)k * 512 + n] : selfW[(size_t)n * 512 + (k - 3072)];
    __nv_bfloat16 hi = __float2bfloat16(w);
    __nv_bfloat16* row = WE + (size_t)n * L2P;
    row[k] = hi;
    row[3584 + k] = __float2bfloat16(w - __bfloat162float(hi));
}

// ---- AC builders: 4-section bf16 operand [hi|hi|hi|lo] + fp32 msg layout ----
__global__ void k_ac1(const int* __restrict__ adj, const float* __restrict__ comb0,
                      const float* __restrict__ comb1, __nv_bfloat16* __restrict__ AE,
                      float* __restrict__ ACm) {
    __shared__ float sc[2][12][6];
    int t = threadIdx.x;
    if (t < 72) { sc[0][t / 6][t % 6] = comb0[t]; sc[1][t / 6][t % 6] = comb1[t]; }
    __syncthreads();
    int b = blockIdx.x;
    int e = blockIdx.y * 256 + t;
    if (e >= 64 * S1) return;
    int n = e / S1, m = e % S1;
    __nv_bfloat16* rowA = AE + ((size_t)b * 64 + n) * 1504;
    if (m < 16) rowA[1488 + m] = __float2bfloat16(0.f);
    bool valid = (n < S1);
    float a[12];
#pragma unroll
    for (int r = 0; r < 12; r++)
        a[r] = valid ? (float)adj[(((size_t)b * 13 + r + 1) * S1 + n) * S1 + m] : 0.f;
#pragma unroll
    for (int q = 0; q < NQ; q++) {
        float s0 = 0.f, s1 = 0.f;
#pragma unroll
        for (int r = 0; r < 12; r++) { s0 += sc[0][r][q] * a[r]; s1 += sc[1][r][q] * a[r]; }
        __nv_bfloat16 hi = __float2bfloat16(s0);
        int c = q * S1 + m;
        rowA[c] = hi; rowA[372 + c] = hi; rowA[744 + c] = hi;
        rowA[1116 + c] = __float2bfloat16(s0 - __bfloat162float(hi));
        if (valid) ACm[(((size_t)b * NQ + q) * S1 + n) * S1 + m] = s1;
    }
}

__global__ void k_ac2(const int* __restrict__ adj, const float* __restrict__ comb0,
                      const float* __restrict__ comb1, __nv_bfloat16* __restrict__ AE,
                      float* __restrict__ ACm) {
    __shared__ float sc[2][12][6];
    int t = threadIdx.x;
    if (t < 72) { sc[0][t / 6][t % 6] = comb0[t]; sc[1][t / 6][t % 6] = comb1[t]; }
    __syncthreads();
    int b = blockIdx.x;
    int e = blockIdx.y * 256 + t;
    if (e >= 64 * S2) return;
    int n = e / S2, m = e % S2;
    __nv_bfloat16* rowA = AE + ((size_t)b * 64 + n) * 1536;
    if (m < 24) rowA[1512 + m] = __float2bfloat16(0.f);
    bool valid = (n < S2);
    int oi = (n == 62) ? 63 : n;
    int oj = (m == 62) ? 63 : m;
    float a[12];
#pragma unroll
    for (int r = 0; r < 12; r++) {
        int v = 0;
        if (valid && oi < 62 && oj < 62)
            v = adj[(((size_t)b * 13 + r + 1) * S1 + oi) * S1 + oj];
        a[r] = (float)v;
    }
    if (valid) {
        int lo2 = min(oi, oj), hi2 = max(oi, oj);
        if (hi2 - lo2 == 2) {
            int ni = lo2 >> 1;
            int ch = ((lo2 & 1) == 0) ? ((ni & 1) ? 12 : 11) : ((ni & 1) ? 11 : 12);
            a[ch - 1] = 1.f;
        }
    }
#pragma unroll
    for (int q = 0; q < NQ; q++) {
        float s0 = 0.f, s1 = 0.f;
#pragma unroll
        for (int r = 0; r < 12; r++) { s0 += sc[0][r][q] * a[r]; s1 += sc[1][r][q] * a[r]; }
        __nv_bfloat16 hi = __float2bfloat16(s0);
        int c = q * S2 + m;
        rowA[c] = hi; rowA[378 + c] = hi; rowA[756 + c] = hi;
        rowA[1134 + c] = __float2bfloat16(s0 - __bfloat162float(hi));
        if (valid) ACm[(((size_t)b * NQ + q) * S2 + n) * S2 + m] = s1;
    }
}

// ---- initial embedding ----
__global__ __launch_bounds__(256)
void k_init(const int* __restrict__ player,
            const float* __restrict__ Ax, const float* __restrict__ Ay,
            const float* __restrict__ Bx, const float* __restrict__ By,
            const float* __restrict__ emb, const float* __restrict__ cW,
            const float* __restrict__ cb, const float* __restrict__ inW,
            const float* __restrict__ inb, float* __restrict__ INIT) {
    __shared__ __align__(16) float As[64][65];
    __shared__ __align__(16) float Bs[64][65];
    int t = threadIdx.x;
    int mb = blockIdx.x * 64, hb = blockIdx.y * 64;
#pragma unroll
    for (int j = 0; j < 16; j++) {
        int i = t + j * 256;
        int r = i >> 6, c = i & 63;
        int m = mb + r, b = m >> 1, p = m & 1;
        float v;
        if (c < 32) {
            float x = p ? Bx[b] : Ax[b];
            float y = p ? By[b] : Ay[b];
            v = fmaxf(cW[c * 2] * x + cW[c * 2 + 1] * y + cb[c], 0.f);
        } else v = emb[player[b * 2 + p] * 32 + (c - 32)];
        As[r][c] = v;
        Bs[r][c] = inW[(hb + r) * 64 + c];
    }
    __syncthreads();
    int tx = t & 15, ty = t >> 4;
    int r0 = ty * 4, c0 = tx * 4;
    float acc[4][4] = {};
    for (int k = 0; k < 64; k++) {
        float av[4], bv[4];
#pragma unroll
        for (int i = 0; i < 4; i++) av[i] = As[r0 + i][k];
#pragma unroll
        for (int j = 0; j < 4; j++) bv[j] = Bs[c0 + j][k];
#pragma unroll
        for (int i = 0; i < 4; i++)
#pragma unroll
            for (int j = 0; j < 4; j++) acc[i][j] += av[i] * bv[j];
    }
#pragma unroll
    for (int i = 0; i < 4; i++)
#pragma unroll
        for (int j = 0; j < 4; j++)
            INIT[(size_t)(mb + r0 + i) * 512 + hb + c0 + j] = acc[i][j] + inb[hb + c0 + j];
}

// ---- int8 quantizers: x = SA*(x1*256 + x0); int8_t explicitly (aarch64 char is unsigned!) ----
__device__ __forceinline__ void quant_row(const float* src, int8_t* dst, float* SA, int m, int lane) {
    float xv[16]; float mx = 0.f;
#pragma unroll
    for (int i = 0; i < 16; i++) { xv[i] = src[lane * 16 + i]; mx = fmaxf(mx, fabsf(xv[i])); }
#pragma unroll
    for (int o = 16; o; o >>= 1) mx = fmaxf(mx, __shfl_xor_sync(0xffffffffu, mx, o));
    mx = fmaxf(mx, 1e-20f);
    float inv = 127.f / mx;
    int8_t o1[16], o0[16];
#pragma unroll
    for (int i = 0; i < 16; i++) {
        float tq = xv[i] * inv;
        float t1 = rintf(tq);
        float t0 = fminf(fmaxf(rintf((tq - t1) * 256.f), -127.f), 127.f);
        o1[i] = (int8_t)t1; o0[i] = (int8_t)t0;
    }
    *(int4*)(dst + (size_t)m * 1024 + lane * 16) = *(int4*)o1;
    *(int4*)(dst + (size_t)m * 1024 + 512 + lane * 16) = *(int4*)o0;
    if (lane == 0) SA[m] = mx / 32512.f;
}

__global__ void k_aq(const float* __restrict__ enc, const float* __restrict__ init,
                     int8_t* __restrict__ A8, float* __restrict__ SA) {
    int w = threadIdx.x >> 5, lane = threadIdx.x & 31;
    int m = blockIdx.x * 8 + w;
    int node = m >> 8, b = m & 255;
    const float* src = (node < NENC) ? enc + ((size_t)b * NENC + node) * HDIM
                                     : init + ((size_t)b * 2 + (node - NENC)) * HDIM;
    quant_row(src, A8, SA, m, lane);
}

__global__ void k_aqT(const float* __restrict__ Tb, int8_t* __restrict__ A8, float* __restrict__ SA) {
    int w = threadIdx.x >> 5, lane = threadIdx.x & 31;
    int local = blockIdx.x * 8 + w;
    int j = local >> 8, b = local & 255;
    quant_row(Tb + ((size_t)b * 4 + j) * HDIM, A8, SA, 15872 + local, lane);
}

__global__ void k_bq(const float* __restrict__ basis, const float* __restrict__ selfW,
                     int8_t* __restrict__ B8, float* __restrict__ SB) {
    int w = threadIdx.x >> 5, lane = threadIdx.x & 31;
    int n = blockIdx.x * 8 + w;
    float xv[16]; float mx = 0.f;
#pragma unroll
    for (int i = 0; i < 16; i++) {
        int k = lane * 16 + i;
        float v;
        if (n < 3072) { int q = n >> 9, j = n & 511; v = basis[((size_t)q * 512 + k) * 512 + j]; }
        else v = selfW[(size_t)(n - 3072) * 512 + k];
        xv[i] = v; mx = fmaxf(mx, fabsf(v));
    }
#pragma unroll
    for (int o = 16; o; o >>= 1) mx = fmaxf(mx, __shfl_xor_sync(0xffffffffu, mx, o));
    mx = fmaxf(mx, 1e-20f);
    float inv = 127.f / mx;
    int8_t o1[16], o0[16];
#pragma unroll
    for (int i = 0; i < 16; i++) {
        float tq = xv[i] * inv;
        float t1 = rintf(tq);
        float t0 = fminf(fmaxf(rintf((tq - t1) * 256.f), -127.f), 127.f);
        o1[i] = (int8_t)t1; o0[i] = (int8_t)t0;
    }
    *(int4*)(B8 + (size_t)n * 1024 + lane * 16) = *(int4*)o1;
    *(int4*)(B8 + (size_t)n * 1024 + 512 + lane * 16) = *(int4*)o0;
    if (lane == 0) SB[n] = mx / 32512.f;
}

// ---- int8 IMMA GEMM: 4 warps x (64x64), KT=64 bytes ----
#define ISTR 80
#define ISTG 10240
__global__ __launch_bounds__(128, 2)
void k_imma(const int8_t* __restrict__ A8, const int8_t* __restrict__ B8,
            const float* __restrict__ SA, const float* __restrict__ SB,
            __nv_bfloat16* __restrict__ O1, __nv_bfloat16* __restrict__ O2,
            float* __restrict__ Of, int Mbase, int KITER, int bxor,
            float secScale, int dual) {
    extern __shared__ __align__(16) char ism[];
    int tid = threadIdx.x;
    int wid = tid >> 5, lane = tid & 31;
    int m0 = Mbase + blockIdx.x * 128;
    int n0 = blockIdx.y * 128;
    int wm = (wid & 1) * 64, wn = (wid >> 1) * 64;

    uint32_t sA0 = smem_u32(ism);
    uint32_t sB0 = sA0 + 4 * ISTG;
    const int8_t* Ag = A8 + (size_t)m0 * 1024;
    const int8_t* Bg = B8 + (size_t)n0 * 1024;

    int acc[4][8][4];
#pragma unroll
    for (int i = 0; i < 4; i++)
#pragma unroll
        for (int j = 0; j < 8; j++)
#pragma unroll
            for (int k = 0; k < 4; k++) acc[i][j][k] = 0;

#pragma unroll
    for (int s = 0; s < 3; s++) {
        int kt = s * 64, bk = kt ^ bxor;
#pragma unroll
        for (int j = 0; j < 4; j++) {
            int i = tid + j * 128;
            int r = i >> 2, c = i & 3;
            cp16(sA0 + s * ISTG + r * ISTR + c * 16, Ag + (size_t)r * 1024 + kt + c * 16);
            cp16(sB0 + s * ISTG + r * ISTR + c * 16, Bg + (size_t)r * 1024 + bk + c * 16);
        }
        CP_COMMIT();
    }

    int a_row = wm + (lane & 15);
    int a_kb  = (lane >> 4) * 16;
    int b_row = wn + ((lane >> 4) * 8) + (lane & 7);
    int b_kb  = ((lane >> 3) & 1) * 16;

    for (int it = 0; it < KITER; it++) {
        int s = it & 3;
        CP_WAIT(2);
        __syncthreads();
        uint32_t aBase = sA0 + s * ISTG;
        uint32_t bBase = sB0 + s * ISTG;
#pragma unroll
        for (int kk = 0; kk < 2; kk++) {
            uint32_t af[4][4];
#pragma unroll
            for (int mt = 0; mt < 4; mt++) {
                uint32_t addr = aBase + (a_row + mt * 16) * ISTR + kk * 32 + a_kb;
                ldsm_x4(af[mt][0], af[mt][1], af[mt][2], af[mt][3], addr);
            }
#pragma unroll
            for (int np = 0; np < 4; np++) {
                uint32_t b0, b1, b2, b3;
                uint32_t addr = bBase + (b_row + np * 16) * ISTR + kk * 32 + b_kb;
                ldsm_x4(b0, b1, b2, b3, addr);
#pragma unroll
                for (int mt = 0; mt < 4; mt++) {
                    imma16832(acc[mt][np * 2],     af[mt], b0, b1);
                    imma16832(acc[mt][np * 2 + 1], af[mt], b2, b3);
                }
            }
        }
        int nit = it + 3;
        if (nit < KITER) {
            int ns = nit & 3;
            int kt = nit * 64, bk = kt ^ bxor;
#pragma unroll
            for (int j = 0; j < 4; j++) {
                int i = tid + j * 128;
                int r = i >> 2, c = i & 3;
                cp16(sA0 + ns * ISTG + r * ISTR + c * 16, Ag + (size_t)r * 1024 + kt + c * 16);
                cp16(sB0 + ns * ISTG + r * ISTR + c * 16, Bg + (size_t)r * 1024 + bk + c * 16);
            }
        }
        CP_COMMIT();
    }

    int crow = m0 + wm + (lane >> 2);
    int ccol = wn + (lane & 3) * 2;
    bool selfPart = (n0 >= 3072);
    float sa[4][2];
#pragma unroll
    for (int mt = 0; mt < 4; mt++) {
        sa[mt][0] = SA[crow + mt * 16] * secScale;
        sa[mt][1] = SA[crow + mt * 16 + 8] * secScale;
    }
#pragma unroll
    for (int nt = 0; nt < 8; nt++) {
        int gc = n0 + ccol + nt * 8;
        float sb0 = SB[gc], sb1 = SB[gc + 1];
#pragma unroll
        for (int mt = 0; mt < 4; mt++) {
            int r1 = crow + mt * 16, r2 = r1 + 8;
            float f00 = __int2float_rn(acc[mt][nt][0]) * sa[mt][0] * sb0;
            float f01 = __int2float_rn(acc[mt][nt][1]) * sa[mt][0] * sb1;
            float f10 = __int2float_rn(acc[mt][nt][2]) * sa[mt][1] * sb0;
            float f11 = __int2float_rn(acc[mt][nt][3]) * sa[mt][1] * sb1;
            if (selfPart) {
                float2 v1; v1.x = f00; v1.y = f01;
                float2 v2; v2.x = f10; v2.y = f11;
                *(float2*)(Of + (size_t)r1 * 512 + gc - 3072) = v1;
                *(float2*)(Of + (size_t)r2 * 512 + gc - 3072) = v2;
            } else if (dual) {
                __nv_bfloat162 l1, l2;
                __nv_bfloat162 h1 = split_hi(f00, f01, l1);
                __nv_bfloat162 h2 = split_hi(f10, f11, l2);
                *(__nv_bfloat162*)(O1 + (size_t)r1 * 3072 + gc) = h1;
                *(__nv_bfloat162*)(O1 + (size_t)r2 * 3072 + gc) = h2;
                *(__nv_bfloat162*)(O2 + (size_t)r1 * 3072 + gc) = l1;
                *(__nv_bfloat162*)(O2 + (size_t)r2 * 3072 + gc) = l2;
            } else {
                __nv_bfloat162 h1, h2;
                h1.x = __float2bfloat16(f00); h1.y = __float2bfloat16(f01);
                h2.x = __float2bfloat16(f10); h2.y = __float2bfloat16(f11);
                *(__nv_bfloat162*)(O1 + (size_t)r1 * 3072 + gc) = h1;
                *(__nv_bfloat162*)(O1 + (size_t)r2 * 3072 + gc) = h2;
            }
        }
    }
}

// ---- combine: 4 sections [ACh|ACh|ACh|ACl] x [YH|YC|YL|YH] ----
#define ASTRIDE 40
#define BSTR 264
#define CSTG 4
template<int S, int RG>
__global__ __launch_bounds__(128, 2)
void k_combine_mma(const __nv_bfloat16* __restrict__ AE,
                   const __nv_bfloat16* __restrict__ YHp,
                   const __nv_bfloat16* __restrict__ YCp,
                   const __nv_bfloat16* __restrict__ YLp,
                   const float* __restrict__ YfH,
                   const float* __restrict__ YfC,
                   float* __restrict__ Z) {
    constexpr int KC = 6 * S;
    constexpr int KE = (S == 62) ? 1504 : 1536;
    constexpr int KIT = KE / 32;
    extern __shared__ char dyn[];
    ull* rp = (ull*)dyn;
    uint32_t aOff = smem_u32(dyn) + KE * 8;
    uint32_t bOff = aOff + CSTG * 5120;

    int tid = threadIdx.x, wid = tid >> 5, lane = tid & 31;
    int b = blockIdx.y;
    int n0c = blockIdx.x * 256;

    for (int k = tid; k < KE; k += 128) {
        int p = k / KC, r = k - p * KC;
        if (p > 3) { p = 0; r = 0; }
        int q = r / S, m = r - q * S;
        int node = (RG == 1) ? m : (m < 58 ? m : (m < 62 ? 62 + (m - 58) : 61));
        const __nv_bfloat16* src = (p == 1) ? YCp : ((p == 2) ? YLp : YHp);
        rp[k] = (ull)(src + ((size_t)node * B + b) * 3072 + q * 512 + n0c);
    }
    __syncthreads();

    const __nv_bfloat16* Ab = AE + (size_t)b * 64 * KE;

    float acc[4][8][4];
#pragma unroll
    for (int i = 0; i < 4; i++)
#pragma unroll
        for (int j = 0; j < 8; j++)
#pragma unroll
            for (int k = 0; k < 4; k++) acc[i][j][k] = 0.f;

#pragma unroll
    for (int s = 0; s < CSTG - 1; s++) {
        int kt = s * 32;
#pragma unroll
        for (int j = 0; j < 2; j++) {
            int i = tid + j * 128;
            int r = i >> 2, c = i & 3;
            cp16(aOff + s * 5120 + (r * ASTRIDE + c * 8) * 2, Ab + (size_t)r * KE + kt + c * 8);
        }
#pragma unroll
        for (int j = 0; j < 8; j++) {
            int i = tid + j * 128;
            int kr = i >> 5, c = i & 31;
            cp16(bOff + s * 16896 + (kr * BSTR + c * 8) * 2, (const char*)rp[kt + kr] + c * 16);
        }
        CP_COMMIT();
    }

    int wn = wid * 64;
    int a_row = lane & 15;
    int a_koff = (lane >> 4) * 8;
    int grp = lane >> 3, lrow = lane & 7;

    for (int it = 0; it < KIT; it++) {
        CP_WAIT(CSTG - 2);
        __syncthreads();
        uint32_t aB = aOff + (it % CSTG) * 5120;
        uint32_t bB = bOff + (it % CSTG) * 16896;
#pragma unroll
        for (int kk = 0; kk < 2; kk++) {
            uint32_t af[4][4];
#pragma unroll
            for (int mt = 0; mt < 4; mt++) {
                uint32_t addr = aB + ((a_row + mt * 16) * ASTRIDE + kk * 16 + a_koff) * 2;
                ldsm_x4(af[mt][0], af[mt][1], af[mt][2], af[mt][3], addr);
            }
#pragma unroll
            for (int np = 0; np < 4; np++) {
                uint32_t b0, b1, b2, b3;
                uint32_t addr = bB + ((kk * 16 + (grp & 1) * 8 + lrow) * BSTR
                                      + wn + np * 16 + (grp >> 1) * 8) * 2;
                ldsm_x4_t(b0, b1, b2, b3, addr);
#pragma unroll
                for (int mt = 0; mt < 4; mt++) {
                    mma16816(acc[mt][np * 2],     af[mt], b0, b1);
                    mma16816(acc[mt][np * 2 + 1], af[mt], b2, b3);
                }
            }
        }
        int nit = it + CSTG - 1;
        if (nit < KIT) {
            int ns = nit % CSTG;
            int kt = nit * 32;
#pragma unroll
            for (int j = 0; j < 2; j++) {
                int i = tid + j * 128;
                int r = i >> 2, c = i & 3;
                cp16(aOff + ns * 5120 + (r * ASTRIDE + c * 8) * 2, Ab + (size_t)r * KE + kt + c * 8);
            }
#pragma unroll
            for (int j = 0; j < 8; j++) {
                int i = tid + j * 128;
                int kr = i >> 5, c = i & 31;
                cp16(bOff + ns * 16896 + (kr * BSTR + c * 8) * 2, (const char*)rp[kt + kr] + c * 16);
            }
        }
        CP_COMMIT();
    }

    int crow = lane >> 2;
    int ccol = wn + (lane & 3) * 2;
#pragma unroll
    for (int mt = 0; mt < 4; mt++) {
#pragma unroll
        for (int nt = 0; nt < 8; nt++) {
            int g = n0c + ccol + nt * 8;
#pragma unroll
            for (int half = 0; half < 2; half++) {
                int n = crow + mt * 16 + half * 8;
                float x = acc[mt][nt][half * 2];
                float y = acc[mt][nt][half * 2 + 1];
                if (n < S) {
                    int node = (RG == 1) ? n : (n < 58 ? n : (n < 62 ? 62 + (n - 58) : 61));
                    size_t off = ((size_t)node * B + b) * 512 + g;
                    float2 o;
                    o.x = fmaxf(x + YfH[off]     + YfC[off],     0.f);
                    o.y = fmaxf(y + YfH[off + 1] + YfC[off + 1], 0.f);
                    *(float2*)(Z + ((size_t)b * S + n) * 512 + g) = o;
                }
            }
        }
    }
}

// ---- layer-2 msg -> split bf16 F ----
__global__ void k_msg(const float* __restrict__ ACm, const float* __restrict__ X,
                      __nv_bfloat16* __restrict__ FE, int nodes, int nRows, int rowBase, int rowStride) {
    int b = blockIdx.y, i = blockIdx.x;
    int row = rowBase + i * rowStride;
    __shared__ __align__(16) ull sA[NQ][64];
    int t = threadIdx.x;
    for (int e = t; e < NQ * nodes; e += 256) {
        int q = e / nodes, m = e % nodes;
        sA[q][m] = dup2(ACm[(((size_t)b * NQ + q) * nodes + row) * nodes + m]);
    }
    __syncthreads();
    ull acc[NQ] = {0ULL, 0ULL, 0ULL, 0ULL, 0ULL, 0ULL};
    const float* xb = X + (size_t)b * nodes * HDIM;
    int h = t * 2;
    for (int m = 0; m < nodes; m++) {
        ull xv = *(const ull*)(xb + (size_t)m * HDIM + h);
#pragma unroll
        for (int q = 0; q < NQ; q++) fma2(acc[q], sA[q][m], xv);
    }
    __nv_bfloat16* Fp = FE + (size_t)(b * nRows + i) * L2P;
#pragma unroll
    for (int q = 0; q < NQ; q++) {
        float v0, v1; unpack2(acc[q], v0, v1);
        __nv_bfloat162 lp;
        __nv_bfloat162 hp = split_hi(v0, v1, lp);
        int col = q * 512 + h;
        *(__nv_bfloat162*)(Fp + col) = hp;
        *(__nv_bfloat162*)(Fp + 3584 + col) = lp;
    }
    {
        ull xv = *(const ull*)(xb + (size_t)row * HDIM + h);
        float v0, v1; unpack2(xv, v0, v1);
        __nv_bfloat162 lp;
        __nv_bfloat162 hp = split_hi(v0, v1, lp);
        int col = 3072 + h;
        *(__nv_bfloat162*)(Fp + col) = hp;
        *(__nv_bfloat162*)(Fp + 3584 + col) = lp;
    }
}

// ---- layer-2 GEMM bf16 split, split-K=7 ----
#define KT 32
#define STAGES 4
#define STAGE_BYTES 10240
__global__ __launch_bounds__(128, 2)
void k_l2mma(const __nv_bfloat16* __restrict__ FE, const __nv_bfloat16* __restrict__ WE,
             float* __restrict__ P, int Mtot) {
    extern __shared__ __align__(16) __nv_bfloat16 sm[];
    int tid = threadIdx.x;
    int wid = tid >> 5, lane = tid & 31;
    int m0 = blockIdx.x * 128, n0 = blockIdx.y * 128;
    int kbase = blockIdx.z * 1536;
    int wm = (wid & 1) * 64, wn = (wid >> 1) * 64;

    uint32_t sA0 = smem_u32(sm);
    uint32_t sB0 = sA0 + STAGES * STAGE_BYTES;
    const __nv_bfloat16* Ag = FE + (size_t)m0 * L2P;
    const __nv_bfloat16* Bg = WE + (size_t)n0 * L2P;

    float acc[4][8][4];
#pragma unroll
    for (int i = 0; i < 4; i++)
#pragma unroll
        for (int j = 0; j < 8; j++)
#pragma unroll
            for (int k = 0; k < 4; k++) acc[i][j][k] = 0.f;

#pragma unroll
    for (int s = 0; s < STAGES - 1; s++) {
        int kt = kbase + s * KT;
        int akt = (kt < 3584) ? kt : kt - 3584;
        int bkt = (kt < 7168) ? kt : kt - 7168;
#pragma unroll
        for (int j = 0; j < 4; j++) {
            int i = tid + j * 128;
            int r = i >> 2, c = i & 3;
            cp16(sA0 + s * STAGE_BYTES + (r * ASTRIDE + c * 8) * 2, Ag + (size_t)r * L2P + akt + c * 8);
            cp16(sB0 + s * STAGE_BYTES + (r * ASTRIDE + c * 8) * 2, Bg + (size_t)r * L2P + bkt + c * 8);
        }
        CP_COMMIT();
    }

    int a_row = wm + (lane & 15);
    int a_koff = (lane >> 4) * 8;
    int b_row = wn + ((lane >> 4) * 8) + (lane & 7);
    int b_koff = ((lane >> 3) & 1) * 8;

    const int KITER = 1536 / KT;
    for (int it = 0; it < KITER; it++) {
        int s = it % STAGES;
        CP_WAIT(STAGES - 2);
        __syncthreads();
        uint32_t aBase = sA0 + s * STAGE_BYTES;
        uint32_t bBase = sB0 + s * STAGE_BYTES;
#pragma unroll
        for (int kk = 0; kk < 2; kk++) {
            uint32_t af[4][4];
#pragma unroll
            for (int mt = 0; mt < 4; mt++) {
                uint32_t addr = aBase + ((a_row + mt * 16) * ASTRIDE + kk * 16 + a_koff) * 2;
                ldsm_x4(af[mt][0], af[mt][1], af[mt][2], af[mt][3], addr);
            }
#pragma unroll
            for (int np = 0; np < 4; np++) {
                uint32_t b0, b1, b2, b3;
                uint32_t addr = bBase + ((b_row + np * 16) * ASTRIDE + kk * 16 + b_koff) * 2;
                ldsm_x4(b0, b1, b2, b3, addr);
#pragma unroll
                for (int mt = 0; mt < 4; mt++) {
                    mma16816(acc[mt][np * 2],     af[mt], b0, b1);
                    mma16816(acc[mt][np * 2 + 1], af[mt], b2, b3);
                }
            }
        }
        int nit = it + STAGES - 1;
        if (nit < KITER) {
            int ns = nit % STAGES;
            int kt = kbase + nit * KT;
            int akt = (kt < 3584) ? kt : kt - 3584;
            int bkt = (kt < 7168) ? kt : kt - 7168;
#pragma unroll
            for (int j = 0; j < 4; j++) {
                int i = tid + j * 128;
                int r = i >> 2, c = i & 3;
                cp16(sA0 + ns * STAGE_BYTES + (r * ASTRIDE + c * 8) * 2, Ag + (size_t)r * L2P + akt + c * 8);
                cp16(sB0 + ns * STAGE_BYTES + (r * ASTRIDE + c * 8) * 2, Bg + (size_t)r * L2P + bkt + c * 8);
            }
        }
        CP_COMMIT();
    }

    float* Pp = P + (size_t)blockIdx.z * Mtot * 512;
    int crow = m0 + wm + (lane >> 2);
    int ccol = wn + (lane & 3) * 2;
#pragma unroll
    for (int mt = 0; mt < 4; mt++) {
#pragma unroll
        for (int nt = 0; nt < 8; nt++) {
            int r1 = crow + mt * 16;
            int gc = n0 + ccol + nt * 8;
            float2 v01; v01.x = acc[mt][nt][0]; v01.y = acc[mt][nt][1];
            float2 v23; v23.x = acc[mt][nt][2]; v23.y = acc[mt][nt][3];
            *(float2*)(Pp + (size_t)r1 * 512 + gc) = v01;
            *(float2*)(Pp + (size_t)(r1 + 8) * 512 + gc) = v23;
        }
    }
}

__global__ void k_l2red(const float* __restrict__ P, float* __restrict__ out, int Mtot) {
    int i = blockIdx.x * 256 + threadIdx.x;
    if (i >= Mtot * 512) return;
    float s = 0.f;
#pragma unroll
    for (int sp = 0; sp < 7; sp++) s += P[(size_t)sp * Mtot * 512 + i];
    out[i] = 1.f / (1.f + expf(-s));
}

__global__ void k_logits(const float* __restrict__ U, const float* __restrict__ tW,
                         const float* __restrict__ tb, float* __restrict__ out) {
    int b = blockIdx.x;
    int w = threadIdx.x >> 5, lane = threadIdx.x & 31;
    if (w >= 11) return;
    const float* black = U + ((size_t)b * 2 + 1) * HDIM;
    const float* white = U + ((size_t)b * 2 + 0) * HDIM;
    const float* row = tW + w * 1024;
    float s = 0.f;
    for (int j = lane; j < HDIM; j += 32)
        s += black[j] * row[j] + white[j] * row[HDIM + j];
#pragma unroll
    for (int o = 16; o; o >>= 1) s += __shfl_down_sync(0xffffffffu, s, o);
    if (lane == 0) out[b * 11 + w] = s + tb[w];
}

// ---- host ----
extern "C" void kernel_launch(void* const* d_in, const int* in_sizes, int n_in,
                              void* d_out, int out_size) {
    int s = (n_in >= 21 && in_sizes[1] == 1) ? 1 : 0;
    const int*   player = (const int*)d_in[0];
    const float* enc    = (const float*)d_in[1 + s];
    const int*   adj    = (const int*)d_in[2 + s];
    const float* Ax     = (const float*)d_in[3 + s];
    const float* Ay     = (const float*)d_in[4 + s];
    const float* Bx     = (const float*)d_in[5 + s];
    const float* By     = (const float*)d_in[6 + s];
    const float* emb    = (const float*)d_in[7 + s];
    const float* coordW = (const float*)d_in[8 + s];
    const float* coordB = (const float*)d_in[9 + s];
    const float* inW    = (const float*)d_in[10 + s];
    const float* inB    = (const float*)d_in[11 + s];
    const float* basis0 = (const float*)d_in[12 + s];
    const float* comb0  = (const float*)d_in[13 + s];
    const float* self0  = (const float*)d_in[14 + s];
    const float* basis1 = (const float*)d_in[15 + s];
    const float* comb1  = (const float*)d_in[16 + s];
    const float* self1  = (const float*)d_in[17 + s];
    const float* typeW  = (const float*)d_in[18 + s];
    const float* typeB  = (const float*)d_in[19 + s];

    float* base = nullptr;
    cudaGetSymbolAddress((void**)&base, g_scratch);
    __nv_bfloat16* CW1E = (__nv_bfloat16*)base;
    float* INIT = base + 1835008;
    float* Z1   = base + 2097152;
    float* Z2   = base + 10223616;
    float* Tb   = base + 18481152;
    float* U    = base + 19005440;
    float* AC1m = base + 19267584;
    float* AC2m = base + 25171968;
    __nv_bfloat16* FE = (__nv_bfloat16*)(base + 31269888);
    int8_t* A8  = (int8_t*)(base + 34939904);
    int8_t* B8  = (int8_t*)(base + 39265280);
    float* SA   = base + 40182784;
    float* SB   = base + 40200192;
    __nv_bfloat16* YH  = (__nv_bfloat16*)(base + 40204288);
    __nv_bfloat16* YC  = (__nv_bfloat16*)(base + 66156544);
    __nv_bfloat16* YL  = (__nv_bfloat16*)(base + 92108800);
    float* YfH  = base + 118061056;
    float* YfC  = base + 126711808;
    __nv_bfloat16* A1E = (__nv_bfloat16*)(base + 135362560);
    __nv_bfloat16* A2E = (__nv_bfloat16*)(base + 147683328);
    float* P    = base + 160266240;

    const int i_smem = 8 * ISTG;
    const int l2_smem = 2 * STAGES * STAGE_BYTES;
    const int c1_smem = 1504 * 8 + CSTG * (5120 + 16896);
    const int c2_smem = 1536 * 8 + CSTG * (5120 + 16896);

    static cudaStream_t s2 = nullptr;
    static cudaEvent_t evA = nullptr, evB = nullptr, evC = nullptr;
    static int once = 0;
    if (!once) {
        cudaFuncSetAttribute(k_imma, cudaFuncAttributeMaxDynamicSharedMemorySize, i_smem);
        cudaFuncSetAttribute(k_l2mma, cudaFuncAttributeMaxDynamicSharedMemorySize, l2_smem);
        cudaFuncSetAttribute(k_combine_mma<62, 1>, cudaFuncAttributeMaxDynamicSharedMemorySize, c1_smem);
        cudaFuncSetAttribute(k_combine_mma<63, 2>, cudaFuncAttributeMaxDynamicSharedMemorySize, c2_smem);
        cudaStreamCreateWithFlags(&s2, cudaStreamNonBlocking);
        cudaEventCreateWithFlags(&evA, cudaEventDisableTiming);
        cudaEventCreateWithFlags(&evB, cudaEventDisableTiming);
        cudaEventCreateWithFlags(&evC, cudaEventDisableTiming);
        once = 1;
    }

    cudaEventRecord(evA, 0);
    cudaStreamWaitEvent(s2, evA, 0);

    k_bq<<<448, 256, 0, s2>>>(basis0, self0, B8, SB);
    cudaEventRecord(evB, s2);

    k_init<<<dim3(8, 8), 256>>>(player, Ax, Ay, Bx, By, emb, coordW, coordB, inW, inB, INIT);
    k_aq<<<1984, 256>>>(enc, INIT, A8, SA);

    cudaStreamWaitEvent(0, evB, 0);
    k_imma<<<dim3(124, 28), 128, i_smem>>>(A8, B8, SA, SB, YH, YL, YfH, 0, 8, 0, 65536.f, 1);
    k_imma<<<dim3(124, 28), 128, i_smem>>>(A8, B8, SA, SB, YC, YC, YfC, 0, 16, 512, 256.f, 0);

    k_ac1<<<dim3(B, 16), 256, 0, s2>>>(adj, comb0, comb1, A1E, AC1m);
    k_ac2<<<dim3(B, 16), 256, 0, s2>>>(adj, comb0, comb1, A2E, AC2m);
    k_build_cw1e<<<(HDIM * KDIM + 255) / 256, 256, 0, s2>>>(basis1, self1, CW1E);
    cudaEventRecord(evC, s2);
    cudaStreamWaitEvent(0, evC, 0);

    k_combine_mma<62, 1><<<dim3(2, B), 128, c1_smem>>>(A1E, YH, YC, YL, YfH, YfC, Z1);
    k_msg<<<dim3(4, B), 256>>>(AC1m, Z1, FE, S1, 4, 58, 1);
    k_l2mma<<<dim3(8, 4, 7), 128, l2_smem>>>(FE, CW1E, P, 1024);
    k_l2red<<<(1024 * 512 + 255) / 256, 256>>>(P, Tb, 1024);

    k_aqT<<<128, 256>>>(Tb, A8, SA);
    k_imma<<<dim3(8, 28), 128, i_smem>>>(A8, B8, SA, SB, YH, YL, YfH, 15872, 8, 0, 65536.f, 1);
    k_imma<<<dim3(8, 28), 128, i_smem>>>(A8, B8, SA, SB, YC, YC, YfC, 15872, 16, 512, 256.f, 0);

    k_combine_mma<63, 2><<<dim3(2, B), 128, c2_smem>>>(A2E, YH, YC, YL, YfH, YfC, Z2);
    k_msg<<<dim3(2, B), 256>>>(AC2m, Z2, FE, S2, 2, 60, 2);
    k_l2mma<<<dim3(4, 4, 7), 128, l2_smem>>>(FE, CW1E, P, 512);
    k_l2red<<<(512 * 512 + 255) / 256, 256>>>(P, U, 512);

    k_logits<<<B, 352>>>(U, typeW, typeB, (float*)d_out);
}

// round 16
// speedup vs baseline: 2.0611x; 2.0611x over previous
#include <cuda_runtime.h>
#include <cuda_bf16.h>
#include <math.h>
#include <stdint.h>

#define B      256
#define HDIM   512
#define NENC   60
#define S1     62
#define S2     63
#define NQ     6
#define KDIM   3584      // 6*512 + 512
#define KEXT   1536      // Y-GEMM 3-term split K: [hi|hi|lo] x [hi|lo|hi]
#define APITCH 1024      // A_ext storage pitch [hi|lo]
#define BPITCH 1024      // B_ext storage pitch [hi|lo]
#define L2P    7168      // layer-2 split storage pitch [hi(3584)|lo(3584)]

typedef unsigned long long ull;

// ---------------- scratch (float offsets) ----------------
static __device__ float g_scratch[185441792];

// ---------------- helpers ----------------
__device__ __forceinline__ ull dup2(float a) {
    ull d; asm("mov.b64 %0, {%1, %1};" : "=l"(d) : "f"(a)); return d;
}
__device__ __forceinline__ void fma2(ull &acc, ull a, ull b) {
    asm("fma.rn.f32x2 %0, %1, %2, %0;" : "+l"(acc) : "l"(a), "l"(b));
}
__device__ __forceinline__ void unpack2(ull v, float &lo, float &hi) {
    asm("mov.b64 {%0, %1}, %2;" : "=f"(lo), "=f"(hi) : "l"(v));
}
__device__ __forceinline__ uint32_t smem_u32(const void* p) {
    uint32_t a;
    asm("{ .reg .u64 t; cvta.to.shared.u64 t, %1; cvt.u32.u64 %0, t; }" : "=r"(a) : "l"(p));
    return a;
}
__device__ __forceinline__ void cp16(uint32_t s, const void* g) {
    asm volatile("cp.async.cg.shared.global [%0], [%1], 16;" :: "r"(s), "l"(g));
}
#define CP_COMMIT() asm volatile("cp.async.commit_group;" ::: "memory")
#define CP_WAIT(n)  asm volatile("cp.async.wait_group %0;" :: "n"(n) : "memory")

__device__ __forceinline__ void ldsm_x4(uint32_t &r0, uint32_t &r1, uint32_t &r2, uint32_t &r3, uint32_t addr) {
    asm volatile("ldmatrix.sync.aligned.m8n8.x4.shared.b16 {%0,%1,%2,%3}, [%4];"
        : "=r"(r0), "=r"(r1), "=r"(r2), "=r"(r3) : "r"(addr));
}
__device__ __forceinline__ void ldsm_x4_t(uint32_t &r0, uint32_t &r1, uint32_t &r2, uint32_t &r3, uint32_t addr) {
    asm volatile("ldmatrix.sync.aligned.m8n8.x4.trans.shared.b16 {%0,%1,%2,%3}, [%4];"
        : "=r"(r0), "=r"(r1), "=r"(r2), "=r"(r3) : "r"(addr));
}
__device__ __forceinline__ void mma16816(float* d, const uint32_t* a, uint32_t b0, uint32_t b1) {
    asm volatile("mma.sync.aligned.m16n8k16.row.col.f32.bf16.bf16.f32 "
        "{%0,%1,%2,%3}, {%4,%5,%6,%7}, {%8,%9}, {%0,%1,%2,%3};"
        : "+f"(d[0]), "+f"(d[1]), "+f"(d[2]), "+f"(d[3])
        : "r"(a[0]), "r"(a[1]), "r"(a[2]), "r"(a[3]), "r"(b0), "r"(b1));
}
__device__ __forceinline__ __nv_bfloat162 split_hi(float v0, float v1, __nv_bfloat162 &lo) {
    __nv_bfloat16 h0 = __float2bfloat16(v0);
    __nv_bfloat16 h1 = __float2bfloat16(v1);
    lo.x = __float2bfloat16(v0 - __bfloat162float(h0));
    lo.y = __float2bfloat16(v1 - __bfloat162float(h1));
    __nv_bfloat162 hi; hi.x = h0; hi.y = h1;
    return hi;
}

// ---------------- CW1E: layer-2 weight, split bf16 [n][k] (pitch 7168) ----------------
__global__ void k_build_cw1e(const float* __restrict__ basis, const float* __restrict__ selfW,
                             __nv_bfloat16* __restrict__ WE) {
    int idx = blockIdx.x * 256 + threadIdx.x;
    if (idx >= HDIM * KDIM) return;
    int n = idx / KDIM;
    int k = idx - n * KDIM;
    float w = (k < 3072) ? basis[(size_t)k * 512 + n]
                         : selfW[(size_t)n * 512 + (k - 3072)];
    __nv_bfloat16 hi = __float2bfloat16(w);
    float lo = w - __bfloat162float(hi);
    __nv_bfloat16* row = WE + (size_t)n * L2P;
    row[k] = hi;
    row[3584 + k] = __float2bfloat16(lo);
}

// ---------------- AC builders ----------------
__global__ void k_ac1(const int* __restrict__ adj, const float* __restrict__ comb0,
                      const float* __restrict__ comb1, __nv_bfloat16* __restrict__ AE,
                      float* __restrict__ ACm) {
    __shared__ float sc[2][12][6];
    int t = threadIdx.x;
    if (t < 72) { sc[0][t / 6][t % 6] = comb0[t]; sc[1][t / 6][t % 6] = comb1[t]; }
    __syncthreads();
    int b = blockIdx.x;
    int e = blockIdx.y * 256 + t;
    if (e >= 64 * S1) return;
    int n = e / S1, m = e % S1;
    __nv_bfloat16* rowA = AE + ((size_t)b * 64 + n) * 1120;
    if (m < 4) rowA[1116 + m] = __float2bfloat16(0.f);
    bool valid = (n < S1);
    float a[12];
#pragma unroll
    for (int r = 0; r < 12; r++)
        a[r] = valid ? (float)adj[(((size_t)b * 13 + r + 1) * S1 + n) * S1 + m] : 0.f;
#pragma unroll
    for (int q = 0; q < NQ; q++) {
        float s0 = 0.f, s1 = 0.f;
#pragma unroll
        for (int r = 0; r < 12; r++) { s0 += sc[0][r][q] * a[r]; s1 += sc[1][r][q] * a[r]; }
        __nv_bfloat16 hi = __float2bfloat16(s0);
        float lo = s0 - __bfloat162float(hi);
        int c = q * S1 + m;
        rowA[c] = hi;
        rowA[372 + c] = hi;
        rowA[744 + c] = __float2bfloat16(lo);
        if (valid)
            ACm[(((size_t)b * NQ + q) * S1 + n) * S1 + m] = s1;
    }
}

__global__ void k_ac2(const int* __restrict__ adj, const float* __restrict__ comb0,
                      const float* __restrict__ comb1, __nv_bfloat16* __restrict__ AE,
                      float* __restrict__ ACm) {
    __shared__ float sc[2][12][6];
    int t = threadIdx.x;
    if (t < 72) { sc[0][t / 6][t % 6] = comb0[t]; sc[1][t / 6][t % 6] = comb1[t]; }
    __syncthreads();
    int b = blockIdx.x;
    int e = blockIdx.y * 256 + t;
    if (e >= 64 * S2) return;
    int n = e / S2, m = e % S2;
    __nv_bfloat16* rowA = AE + ((size_t)b * 64 + n) * 1152;
    if (m < 18) rowA[1134 + m] = __float2bfloat16(0.f);
    bool valid = (n < S2);
    int oi = (n == 62) ? 63 : n;
    int oj = (m == 62) ? 63 : m;
    float a[12];
#pragma unroll
    for (int r = 0; r < 12; r++) {
        int v = 0;
        if (valid && oi < 62 && oj < 62)
            v = adj[(((size_t)b * 13 + r + 1) * S1 + oi) * S1 + oj];
        a[r] = (float)v;
    }
    if (valid) {
        int lo2 = min(oi, oj), hi2 = max(oi, oj);
        if (hi2 - lo2 == 2) {
            int ni = lo2 >> 1;
            int ch = ((lo2 & 1) == 0) ? ((ni & 1) ? 12 : 11) : ((ni & 1) ? 11 : 12);
            a[ch - 1] = 1.f;
        }
    }
#pragma unroll
    for (int q = 0; q < NQ; q++) {
        float s0 = 0.f, s1 = 0.f;
#pragma unroll
        for (int r = 0; r < 12; r++) { s0 += sc[0][r][q] * a[r]; s1 += sc[1][r][q] * a[r]; }
        __nv_bfloat16 hi = __float2bfloat16(s0);
        float lo = s0 - __bfloat162float(hi);
        int c = q * S2 + m;
        rowA[c] = hi;
        rowA[378 + c] = hi;
        rowA[756 + c] = __float2bfloat16(lo);
        if (valid)
            ACm[(((size_t)b * NQ + q) * S2 + n) * S2 + m] = s1;
    }
}

// ---------------- initial embedding (fused feature + GEMM) ----------------
__global__ __launch_bounds__(256)
void k_init(const int* __restrict__ player,
            const float* __restrict__ Ax, const float* __restrict__ Ay,
            const float* __restrict__ Bx, const float* __restrict__ By,
            const float* __restrict__ emb, const float* __restrict__ cW,
            const float* __restrict__ cb, const float* __restrict__ inW,
            const float* __restrict__ inb, float* __restrict__ INIT) {
    __shared__ __align__(16) float As[64][65];
    __shared__ __align__(16) float Bs[64][65];
    int t = threadIdx.x;
    int mb = blockIdx.x * 64, hb = blockIdx.y * 64;
#pragma unroll
    for (int j = 0; j < 16; j++) {
        int i = t + j * 256;
        int r = i >> 6, c = i & 63;
        int m = mb + r;
        int b = m >> 1, p = m & 1;
        float v;
        if (c < 32) {
            float x = p ? Bx[b] : Ax[b];
            float y = p ? By[b] : Ay[b];
            v = fmaxf(cW[c * 2] * x + cW[c * 2 + 1] * y + cb[c], 0.f);
        } else {
            v = emb[player[b * 2 + p] * 32 + (c - 32)];
        }
        As[r][c] = v;
        Bs[r][c] = inW[(hb + r) * 64 + c];
    }
    __syncthreads();
    int tx = t & 15, ty = t >> 4;
    int r0 = ty * 4, c0 = tx * 4;
    float acc[4][4] = {};
    for (int k = 0; k < 64; k++) {
        float av[4], bv[4];
#pragma unroll
        for (int i = 0; i < 4; i++) av[i] = As[r0 + i][k];
#pragma unroll
        for (int j = 0; j < 4; j++) bv[j] = Bs[c0 + j][k];
#pragma unroll
        for (int i = 0; i < 4; i++)
#pragma unroll
            for (int j = 0; j < 4; j++) acc[i][j] += av[i] * bv[j];
    }
#pragma unroll
    for (int i = 0; i < 4; i++)
#pragma unroll
        for (int j = 0; j < 4; j++)
            INIT[(size_t)(mb + r0 + i) * 512 + hb + c0 + j] = acc[i][j] + inb[hb + c0 + j];
}

// ---------------- A_ext builder (bf16 split [hi|lo], pitch 1024) ----------------
__global__ void k_aext(const float* __restrict__ enc, const float* __restrict__ init,
                       __nv_bfloat16* __restrict__ A) {
    size_t i = (size_t)blockIdx.x * 256 + threadIdx.x;
    if (i >= (size_t)62 * B * HDIM) return;
    int m = (int)(i >> 9);
    int h = (int)(i & 511);
    int node = m >> 8, b = m & 255;
    float x = (node < NENC) ? enc[((size_t)b * NENC + node) * HDIM + h]
                            : init[((size_t)b * 2 + (node - NENC)) * HDIM + h];
    __nv_bfloat16 hi = __float2bfloat16(x);
    float lo = x - __bfloat162float(hi);
    __nv_bfloat16* row = A + (size_t)m * APITCH;
    row[h] = hi;
    row[512 + h] = __float2bfloat16(lo);
}

// ---------------- B_ext builder (bf16 split [hi|lo], pitch 1024) ----------------
__global__ void k_bext(const float* __restrict__ basis, const float* __restrict__ selfW,
                       __nv_bfloat16* __restrict__ Bm) {
    size_t i = (size_t)blockIdx.x * 256 + threadIdx.x;
    if (i >= (size_t)KDIM * HDIM) return;
    int n = (int)(i >> 9);
    int k = (int)(i & 511);
    float w;
    if (n < 3072) {
        int q = n >> 9, j = n & 511;
        w = basis[((size_t)q * 512 + k) * 512 + j];
    } else {
        w = selfW[(size_t)(n - 3072) * 512 + k];
    }
    __nv_bfloat16 hi = __float2bfloat16(w);
    float lo = w - __bfloat162float(hi);
    __nv_bfloat16* row = Bm + (size_t)n * BPITCH;
    row[k] = hi;
    row[512 + k] = __float2bfloat16(lo);
}

// ---------------- Y-GEMM mma.sync: 3-term split, dedup [hi|lo] operands ----------------
#define KT 32
#define STAGES 4
#define ASTRIDE 40
#define STAGE_ELT (128 * ASTRIDE)
#define STAGE_BYTES (STAGE_ELT * 2)

__global__ __launch_bounds__(128, 2)
void k_mma(const __nv_bfloat16* __restrict__ A, const __nv_bfloat16* __restrict__ Bm,
           float* __restrict__ C, __nv_bfloat16* __restrict__ YHp,
           __nv_bfloat16* __restrict__ YLp, int Mbase) {
    extern __shared__ __align__(16) __nv_bfloat16 sm[];
    int tid = threadIdx.x;
    int wid = tid >> 5, lane = tid & 31;
    int m0 = Mbase + blockIdx.x * 128;
    int n0 = blockIdx.y * 128;
    int wm = (wid & 1) * 64;
    int wn = (wid >> 1) * 64;

    uint32_t sA0 = smem_u32(sm);
    uint32_t sB0 = sA0 + STAGES * STAGE_BYTES;

    const __nv_bfloat16* Ag = A + (size_t)m0 * APITCH;
    const __nv_bfloat16* Bg = Bm + (size_t)n0 * BPITCH;

    float acc[4][8][4];
#pragma unroll
    for (int i = 0; i < 4; i++)
#pragma unroll
        for (int j = 0; j < 8; j++)
#pragma unroll
            for (int k = 0; k < 4; k++) acc[i][j][k] = 0.f;

#pragma unroll
    for (int s = 0; s < STAGES - 1; s++) {
        int kt = s * KT;
        int akt = (kt < 512) ? kt : kt - 512;      // logical [hi|hi|lo]
        int bkt = (kt < 1024) ? kt : kt - 1024;    // logical [hi|lo|hi]
#pragma unroll
        for (int j = 0; j < 4; j++) {
            int i = tid + j * 128;
            int r = i >> 2, c = i & 3;
            cp16(sA0 + s * STAGE_BYTES + (r * ASTRIDE + c * 8) * 2, Ag + (size_t)r * APITCH + akt + c * 8);
            cp16(sB0 + s * STAGE_BYTES + (r * ASTRIDE + c * 8) * 2, Bg + (size_t)r * BPITCH + bkt + c * 8);
        }
        CP_COMMIT();
    }

    int a_row = wm + (lane & 15);
    int a_koff = (lane >> 4) * 8;
    int b_row = wn + ((lane >> 4) * 8) + (lane & 7);
    int b_koff = ((lane >> 3) & 1) * 8;

    const int KITER = KEXT / KT;   // 48
    for (int it = 0; it < KITER; it++) {
        int s = it % STAGES;
        CP_WAIT(STAGES - 2);
        __syncthreads();

        uint32_t aBase = sA0 + s * STAGE_BYTES;
        uint32_t bBase = sB0 + s * STAGE_BYTES;
#pragma unroll
        for (int kk = 0; kk < 2; kk++) {
            uint32_t af[4][4];
#pragma unroll
            for (int mt = 0; mt < 4; mt++) {
                uint32_t addr = aBase + ((a_row + mt * 16) * ASTRIDE + kk * 16 + a_koff) * 2;
                ldsm_x4(af[mt][0], af[mt][1], af[mt][2], af[mt][3], addr);
            }
#pragma unroll
            for (int np = 0; np < 4; np++) {
                uint32_t b0, b1, b2, b3;
                uint32_t addr = bBase + ((b_row + np * 16) * ASTRIDE + kk * 16 + b_koff) * 2;
                ldsm_x4(b0, b1, b2, b3, addr);
#pragma unroll
                for (int mt = 0; mt < 4; mt++) {
                    mma16816(acc[mt][np * 2],     af[mt], b0, b1);
                    mma16816(acc[mt][np * 2 + 1], af[mt], b2, b3);
                }
            }
        }
        int nit = it + STAGES - 1;
        if (nit < KITER) {
            int ns = nit % STAGES;
            int kt = nit * KT;
            int akt = (kt < 512) ? kt : kt - 512;
            int bkt = (kt < 1024) ? kt : kt - 1024;
#pragma unroll
            for (int j = 0; j < 4; j++) {
                int i = tid + j * 128;
                int r = i >> 2, c = i & 3;
                cp16(sA0 + ns * STAGE_BYTES + (r * ASTRIDE + c * 8) * 2, Ag + (size_t)r * APITCH + akt + c * 8);
                cp16(sB0 + ns * STAGE_BYTES + (r * ASTRIDE + c * 8) * 2, Bg + (size_t)r * BPITCH + bkt + c * 8);
            }
        }
        CP_COMMIT();
    }

    int crow = m0 + wm + (lane >> 2);
    int ccol = wn + (lane & 3) * 2;
    bool selfPart = (n0 >= 3072);
#pragma unroll
    for (int mt = 0; mt < 4; mt++) {
#pragma unroll
        for (int nt = 0; nt < 8; nt++) {
            int r1 = crow + mt * 16;
            int r2 = r1 + 8;
            int gc = n0 + ccol + nt * 8;
            float2 v01; v01.x = acc[mt][nt][0]; v01.y = acc[mt][nt][1];
            float2 v23; v23.x = acc[mt][nt][2]; v23.y = acc[mt][nt][3];
            if (selfPart) {
                *(float2*)(C + (size_t)r1 * KDIM + gc) = v01;
                *(float2*)(C + (size_t)r2 * KDIM + gc) = v23;
            } else {
                __nv_bfloat162 lp1, lp2;
                __nv_bfloat162 hp1 = split_hi(v01.x, v01.y, lp1);
                __nv_bfloat162 hp2 = split_hi(v23.x, v23.y, lp2);
                *(__nv_bfloat162*)(YHp + (size_t)r1 * 3072 + gc) = hp1;
                *(__nv_bfloat162*)(YHp + (size_t)r2 * 3072 + gc) = hp2;
                *(__nv_bfloat162*)(YLp + (size_t)r1 * 3072 + gc) = lp1;
                *(__nv_bfloat162*)(YLp + (size_t)r2 * 3072 + gc) = lp2;
            }
        }
    }
}

// ---------------- combine via mma.sync: 4 warps x (64x64), 128 threads ----------------
#define BSTR 264
#define CSTG 4
template<int S, int RG>
__global__ __launch_bounds__(128, 2)
void k_combine_mma(const __nv_bfloat16* __restrict__ AE,
                   const __nv_bfloat16* __restrict__ YHp,
                   const __nv_bfloat16* __restrict__ YLp,
                   const float* __restrict__ Yf,
                   float* __restrict__ Z) {
    constexpr int KC = 6 * S;
    constexpr int KE = (S == 62) ? 1120 : 1152;
    constexpr int KIT = KE / 32;
    constexpr int RPB = KE * 8;
    extern __shared__ char dyn[];
    ull* rp = (ull*)dyn;
    uint32_t aOff = smem_u32(dyn) + RPB;
    uint32_t bOff = aOff + CSTG * 5120;

    int tid = threadIdx.x, wid = tid >> 5, lane = tid & 31;
    int b = blockIdx.y;
    int n0c = blockIdx.x * 256;

    for (int k = tid; k < KE; k += 128) {
        int p = k / KC, r = k - p * KC;
        if (p > 2) { p = 0; r = 0; }
        int q = r / S, m = r - q * S;
        int node = (RG == 1) ? m : (m < 58 ? m : (m < 62 ? 62 + (m - 58) : 61));
        const __nv_bfloat16* src = (p == 1) ? YLp : YHp;
        rp[k] = (ull)(src + ((size_t)node * B + b) * 3072 + q * 512 + n0c);
    }
    __syncthreads();

    const __nv_bfloat16* Ab = AE + (size_t)b * 64 * KE;

    float acc[4][8][4];
#pragma unroll
    for (int i = 0; i < 4; i++)
#pragma unroll
        for (int j = 0; j < 8; j++)
#pragma unroll
            for (int k = 0; k < 4; k++) acc[i][j][k] = 0.f;

#pragma unroll
    for (int s = 0; s < CSTG - 1; s++) {
        int kt = s * 32;
#pragma unroll
        for (int j = 0; j < 2; j++) {
            int i = tid + j * 128;
            int r = i >> 2, c = i & 3;
            cp16(aOff + s * 5120 + (r * ASTRIDE + c * 8) * 2, Ab + (size_t)r * KE + kt + c * 8);
        }
#pragma unroll
        for (int j = 0; j < 8; j++) {
            int i = tid + j * 128;
            int kr = i >> 5, c = i & 31;
            cp16(bOff + s * 16896 + (kr * BSTR + c * 8) * 2, (const char*)rp[kt + kr] + c * 16);
        }
        CP_COMMIT();
    }

    int wn = wid * 64;
    int a_row = lane & 15;
    int a_koff = (lane >> 4) * 8;
    int grp = lane >> 3, lrow = lane & 7;

    for (int it = 0; it < KIT; it++) {
        CP_WAIT(CSTG - 2);
        __syncthreads();
        uint32_t aB = aOff + (it % CSTG) * 5120;
        uint32_t bB = bOff + (it % CSTG) * 16896;
#pragma unroll
        for (int kk = 0; kk < 2; kk++) {
            uint32_t af[4][4];
#pragma unroll
            for (int mt = 0; mt < 4; mt++) {
                uint32_t addr = aB + ((a_row + mt * 16) * ASTRIDE + kk * 16 + a_koff) * 2;
                ldsm_x4(af[mt][0], af[mt][1], af[mt][2], af[mt][3], addr);
            }
#pragma unroll
            for (int np = 0; np < 4; np++) {
                uint32_t b0, b1, b2, b3;
                uint32_t addr = bB + ((kk * 16 + (grp & 1) * 8 + lrow) * BSTR
                                      + wn + np * 16 + (grp >> 1) * 8) * 2;
                ldsm_x4_t(b0, b1, b2, b3, addr);
#pragma unroll
                for (int mt = 0; mt < 4; mt++) {
                    mma16816(acc[mt][np * 2],     af[mt], b0, b1);
                    mma16816(acc[mt][np * 2 + 1], af[mt], b2, b3);
                }
            }
        }
        int nit = it + CSTG - 1;
        if (nit < KIT) {
            int ns = nit % CSTG;
            int kt = nit * 32;
#pragma unroll
            for (int j = 0; j < 2; j++) {
                int i = tid + j * 128;
                int r = i >> 2, c = i & 3;
                cp16(aOff + ns * 5120 + (r * ASTRIDE + c * 8) * 2, Ab + (size_t)r * KE + kt + c * 8);
            }
#pragma unroll
            for (int j = 0; j < 8; j++) {
                int i = tid + j * 128;
                int kr = i >> 5, c = i & 31;
                cp16(bOff + ns * 16896 + (kr * BSTR + c * 8) * 2, (const char*)rp[kt + kr] + c * 16);
            }
        }
        CP_COMMIT();
    }

    int crow = lane >> 2;
    int ccol = wn + (lane & 3) * 2;
#pragma unroll
    for (int mt = 0; mt < 4; mt++) {
#pragma unroll
        for (int nt = 0; nt < 8; nt++) {
            int g = n0c + ccol + nt * 8;
#pragma unroll
            for (int half = 0; half < 2; half++) {
                int n = crow + mt * 16 + half * 8;
                float x = acc[mt][nt][half * 2];
                float y = acc[mt][nt][half * 2 + 1];
                if (n < S) {
                    int node = (RG == 1) ? n : (n < 58 ? n : (n < 62 ? 62 + (n - 58) : 61));
                    const float* sp = Yf + ((size_t)node * B + b) * KDIM + 3072 + g;
                    float2 o;
                    o.x = fmaxf(x + sp[0], 0.f);
                    o.y = fmaxf(y + sp[1], 0.f);
                    *(float2*)(Z + ((size_t)b * S + n) * 512 + g) = o;
                }
            }
        }
    }
}

// ---------------- layer-2 message aggregation -> split bf16 F ----------------
__global__ void k_msg(const float* __restrict__ ACm, const float* __restrict__ X,
                      __nv_bfloat16* __restrict__ FE, int nodes, int nRows, int rowBase, int rowStride) {
    int b = blockIdx.y, i = blockIdx.x;
    int row = rowBase + i * rowStride;
    __shared__ __align__(16) ull sA[NQ][64];
    int t = threadIdx.x;
    for (int e = t; e < NQ * nodes; e += 256) {
        int q = e / nodes, m = e % nodes;
        sA[q][m] = dup2(ACm[(((size_t)b * NQ + q) * nodes + row) * nodes + m]);
    }
    __syncthreads();
    ull acc[NQ] = {0ULL, 0ULL, 0ULL, 0ULL, 0ULL, 0ULL};
    const float* xb = X + (size_t)b * nodes * HDIM;
    int h = t * 2;
    for (int m = 0; m < nodes; m++) {
        ull xv = *(const ull*)(xb + (size_t)m * HDIM + h);
#pragma unroll
        for (int q = 0; q < NQ; q++) fma2(acc[q], sA[q][m], xv);
    }
    __nv_bfloat16* Fp = FE + (size_t)(b * nRows + i) * L2P;
#pragma unroll
    for (int q = 0; q < NQ; q++) {
        float v0, v1; unpack2(acc[q], v0, v1);
        __nv_bfloat162 lp;
        __nv_bfloat162 hp = split_hi(v0, v1, lp);
        int col = q * 512 + h;
        *(__nv_bfloat162*)(Fp + col) = hp;
        *(__nv_bfloat162*)(Fp + 3584 + col) = lp;
    }
    {
        ull xv = *(const ull*)(xb + (size_t)row * HDIM + h);
        float v0, v1; unpack2(xv, v0, v1);
        __nv_bfloat162 lp;
        __nv_bfloat162 hp = split_hi(v0, v1, lp);
        int col = 3072 + h;
        *(__nv_bfloat162*)(Fp + col) = hp;
        *(__nv_bfloat162*)(Fp + 3584 + col) = lp;
    }
}

// ---------------- layer-2 GEMM: split-bf16 mma with split-K=7 ----------------
__global__ __launch_bounds__(128, 2)
void k_l2mma(const __nv_bfloat16* __restrict__ FE, const __nv_bfloat16* __restrict__ WE,
             float* __restrict__ P, int Mtot) {
    extern __shared__ __align__(16) __nv_bfloat16 sm[];
    int tid = threadIdx.x;
    int wid = tid >> 5, lane = tid & 31;
    int m0 = blockIdx.x * 128;
    int n0 = blockIdx.y * 128;
    int kbase = blockIdx.z * 1536;
    int wm = (wid & 1) * 64;
    int wn = (wid >> 1) * 64;

    uint32_t sA0 = smem_u32(sm);
    uint32_t sB0 = sA0 + STAGES * STAGE_BYTES;

    const __nv_bfloat16* Ag = FE + (size_t)m0 * L2P;
    const __nv_bfloat16* Bg = WE + (size_t)n0 * L2P;

    float acc[4][8][4];
#pragma unroll
    for (int i = 0; i < 4; i++)
#pragma unroll
        for (int j = 0; j < 8; j++)
#pragma unroll
            for (int k = 0; k < 4; k++) acc[i][j][k] = 0.f;

#pragma unroll
    for (int s = 0; s < STAGES - 1; s++) {
        int kt = kbase + s * KT;
        int akt = (kt < 3584) ? kt : kt - 3584;
        int bkt = (kt < 7168) ? kt : kt - 7168;
#pragma unroll
        for (int j = 0; j < 4; j++) {
            int i = tid + j * 128;
            int r = i >> 2, c = i & 3;
            cp16(sA0 + s * STAGE_BYTES + (r * ASTRIDE + c * 8) * 2, Ag + (size_t)r * L2P + akt + c * 8);
            cp16(sB0 + s * STAGE_BYTES + (r * ASTRIDE + c * 8) * 2, Bg + (size_t)r * L2P + bkt + c * 8);
        }
        CP_COMMIT();
    }

    int a_row = wm + (lane & 15);
    int a_koff = (lane >> 4) * 8;
    int b_row = wn + ((lane >> 4) * 8) + (lane & 7);
    int b_koff = ((lane >> 3) & 1) * 8;

    const int KITER = 1536 / KT;
    for (int it = 0; it < KITER; it++) {
        int s = it % STAGES;
        CP_WAIT(STAGES - 2);
        __syncthreads();

        uint32_t aBase = sA0 + s * STAGE_BYTES;
        uint32_t bBase = sB0 + s * STAGE_BYTES;
#pragma unroll
        for (int kk = 0; kk < 2; kk++) {
            uint32_t af[4][4];
#pragma unroll
            for (int mt = 0; mt < 4; mt++) {
                uint32_t addr = aBase + ((a_row + mt * 16) * ASTRIDE + kk * 16 + a_koff) * 2;
                ldsm_x4(af[mt][0], af[mt][1], af[mt][2], af[mt][3], addr);
            }
#pragma unroll
            for (int np = 0; np < 4; np++) {
                uint32_t b0, b1, b2, b3;
                uint32_t addr = bBase + ((b_row + np * 16) * ASTRIDE + kk * 16 + b_koff) * 2;
                ldsm_x4(b0, b1, b2, b3, addr);
#pragma unroll
                for (int mt = 0; mt < 4; mt++) {
                    mma16816(acc[mt][np * 2],     af[mt], b0, b1);
                    mma16816(acc[mt][np * 2 + 1], af[mt], b2, b3);
                }
            }
        }
        int nit = it + STAGES - 1;
        if (nit < KITER) {
            int ns = nit % STAGES;
            int kt = kbase + nit * KT;
            int akt = (kt < 3584) ? kt : kt - 3584;
            int bkt = (kt < 7168) ? kt : kt - 7168;
#pragma unroll
            for (int j = 0; j < 4; j++) {
                int i = tid + j * 128;
                int r = i >> 2, c = i & 3;
                cp16(sA0 + ns * STAGE_BYTES + (r * ASTRIDE + c * 8) * 2, Ag + (size_t)r * L2P + akt + c * 8);
                cp16(sB0 + ns * STAGE_BYTES + (r * ASTRIDE + c * 8) * 2, Bg + (size_t)r * L2P + bkt + c * 8);
            }
        }
        CP_COMMIT();
    }

    float* Pp = P + (size_t)blockIdx.z * Mtot * 512;
    int crow = m0 + wm + (lane >> 2);
    int ccol = wn + (lane & 3) * 2;
#pragma unroll
    for (int mt = 0; mt < 4; mt++) {
#pragma unroll
        for (int nt = 0; nt < 8; nt++) {
            int r1 = crow + mt * 16;
            int gc = n0 + ccol + nt * 8;
            float2 v01; v01.x = acc[mt][nt][0]; v01.y = acc[mt][nt][1];
            float2 v23; v23.x = acc[mt][nt][2]; v23.y = acc[mt][nt][3];
            *(float2*)(Pp + (size_t)r1 * 512 + gc) = v01;
            *(float2*)(Pp + (size_t)(r1 + 8) * 512 + gc) = v23;
        }
    }
}

// ---------------- fused layer-2 reduce + sigmoid + A_ext write (rgcn1 only) ----------------
__global__ void k_l2redA(const float* __restrict__ P, __nv_bfloat16* __restrict__ A) {
    int i = blockIdx.x * 256 + threadIdx.x;       // over 4*B*512
    if (i >= 4 * B * 512) return;
    int m = i >> 9, h = i & 511;
    int b = m >> 2, j = m & 3;
    float s = 0.f;
#pragma unroll
    for (int sp = 0; sp < 7; sp++) s += P[(size_t)sp * 1024 * 512 + i];
    float x = 1.f / (1.f + expf(-s));
    __nv_bfloat16 hi = __float2bfloat16(x);
    float lo = x - __bfloat162float(hi);
    __nv_bfloat16* row = A + (size_t)((62 + j) * B + b) * APITCH;
    row[h] = hi;
    row[512 + h] = __float2bfloat16(lo);
}

// ---------------- layer-2 reduce + sigmoid (rgcn2 -> U) ----------------
__global__ void k_l2red(const float* __restrict__ P, float* __restrict__ out, int Mtot) {
    int i = blockIdx.x * 256 + threadIdx.x;
    if (i >= Mtot * 512) return;
    float s = 0.f;
#pragma unroll
    for (int sp = 0; sp < 7; sp++) s += P[(size_t)sp * Mtot * 512 + i];
    out[i] = 1.f / (1.f + expf(-s));
}

// ---------------- final logits ----------------
__global__ void k_logits(const float* __restrict__ U, const float* __restrict__ tW,
                         const float* __restrict__ tb, float* __restrict__ out) {
    int b = blockIdx.x;
    int w = threadIdx.x >> 5, lane = threadIdx.x & 31;
    if (w >= 11) return;
    const float* black = U + ((size_t)b * 2 + 1) * HDIM;
    const float* white = U + ((size_t)b * 2 + 0) * HDIM;
    const float* row = tW + w * 1024;
    float s = 0.f;
    for (int j = lane; j < HDIM; j += 32)
        s += black[j] * row[j] + white[j] * row[HDIM + j];
#pragma unroll
    for (int o = 16; o; o >>= 1) s += __shfl_down_sync(0xffffffffu, s, o);
    if (lane == 0) out[b * 11 + w] = s + tb[w];
}

// ---------------- host ----------------
extern "C" void kernel_launch(void* const* d_in, const int* in_sizes, int n_in,
                              void* d_out, int out_size) {
    int s = (n_in >= 21 && in_sizes[1] == 1) ? 1 : 0;

    const int*   player = (const int*)d_in[0];
    const float* enc    = (const float*)d_in[1 + s];
    const int*   adj    = (const int*)d_in[2 + s];
    const float* Ax     = (const float*)d_in[3 + s];
    const float* Ay     = (const float*)d_in[4 + s];
    const float* Bx     = (const float*)d_in[5 + s];
    const float* By     = (const float*)d_in[6 + s];
    const float* emb    = (const float*)d_in[7 + s];
    const float* coordW = (const float*)d_in[8 + s];
    const float* coordB = (const float*)d_in[9 + s];
    const float* inW    = (const float*)d_in[10 + s];
    const float* inB    = (const float*)d_in[11 + s];
    const float* basis0 = (const float*)d_in[12 + s];
    const float* comb0  = (const float*)d_in[13 + s];
    const float* self0  = (const float*)d_in[14 + s];
    const float* basis1 = (const float*)d_in[15 + s];
    const float* comb1  = (const float*)d_in[16 + s];
    const float* self1  = (const float*)d_in[17 + s];
    const float* typeW  = (const float*)d_in[18 + s];
    const float* typeB  = (const float*)d_in[19 + s];

    float* base = nullptr;
    cudaGetSymbolAddress((void**)&base, g_scratch);
    __nv_bfloat16* CW1E = (__nv_bfloat16*)base;
    float* INIT = base + 1835008;
    float* Y    = base + 2129920;
    float* Z1   = base + 62685184;
    float* Z2   = base + 70811648;
    float* U    = base + 79593472;
    float* AC1m = base + 79855616;
    float* AC2m = base + 85760000;
    __nv_bfloat16* FE = (__nv_bfloat16*)(base + 91856384);
    __nv_bfloat16* AEXT = (__nv_bfloat16*)(base + 95526400);
    __nv_bfloat16* BEXT = (__nv_bfloat16*)(base + 108502528);
    __nv_bfloat16* YH   = (__nv_bfloat16*)(base + 111255040);
    __nv_bfloat16* YL   = (__nv_bfloat16*)(base + 137207296);
    __nv_bfloat16* A1E  = (__nv_bfloat16*)(base + 163159552);
    __nv_bfloat16* A2E  = (__nv_bfloat16*)(base + 172334592);
    float* P    = base + 181771776;

    const int mma_smem = 2 * STAGES * STAGE_BYTES;           // 81920
    const int c1_smem = 1120 * 8 + CSTG * (5120 + 16896);    // 97024
    const int c2_smem = 1152 * 8 + CSTG * (5120 + 16896);    // 97280

    static cudaStream_t s2 = nullptr;
    static cudaEvent_t evA = nullptr, evB = nullptr, evC = nullptr;
    static int once = 0;
    if (!once) {
        cudaFuncSetAttribute(k_mma, cudaFuncAttributeMaxDynamicSharedMemorySize, mma_smem);
        cudaFuncSetAttribute(k_l2mma, cudaFuncAttributeMaxDynamicSharedMemorySize, mma_smem);
        cudaFuncSetAttribute(k_combine_mma<62, 1>, cudaFuncAttributeMaxDynamicSharedMemorySize, c1_smem);
        cudaFuncSetAttribute(k_combine_mma<63, 2>, cudaFuncAttributeMaxDynamicSharedMemorySize, c2_smem);
        cudaStreamCreateWithFlags(&s2, cudaStreamNonBlocking);
        cudaEventCreateWithFlags(&evA, cudaEventDisableTiming);
        cudaEventCreateWithFlags(&evB, cudaEventDisableTiming);
        cudaEventCreateWithFlags(&evC, cudaEventDisableTiming);
        once = 1;
    }

    cudaEventRecord(evA, 0);
    cudaStreamWaitEvent(s2, evA, 0);

    k_bext<<<(KDIM * HDIM + 255) / 256, 256, 0, s2>>>(basis0, self0, BEXT);
    cudaEventRecord(evB, s2);

    k_init<<<dim3(8, 8), 256>>>(player, Ax, Ay, Bx, By, emb, coordW, coordB, inW, inB, INIT);
    k_aext<<<(62 * B * HDIM + 255) / 256, 256>>>(enc, INIT, AEXT);

    cudaStreamWaitEvent(0, evB, 0);
    k_mma<<<dim3(62 * B / 128, KDIM / 128), 128, mma_smem>>>(AEXT, BEXT, Y, YH, YL, 0);

    k_ac1<<<dim3(B, 16), 256, 0, s2>>>(adj, comb0, comb1, A1E, AC1m);
    k_ac2<<<dim3(B, 16), 256, 0, s2>>>(adj, comb0, comb1, A2E, AC2m);
    k_build_cw1e<<<(HDIM * KDIM + 255) / 256, 256, 0, s2>>>(basis1, self1, CW1E);
    cudaEventRecord(evC, s2);
    cudaStreamWaitEvent(0, evC, 0);

    k_combine_mma<62, 1><<<dim3(2, B), 128, c1_smem>>>(A1E, YH, YL, Y, Z1);
    k_msg<<<dim3(4, B), 256>>>(AC1m, Z1, FE, S1, 4, 58, 1);
    k_l2mma<<<dim3(8, 4, 7), 128, mma_smem>>>(FE, CW1E, P, 1024);
    // fused: reduce+sigmoid -> AEXT rows 62..65 directly
    k_l2redA<<<(4 * B * 512 + 255) / 256, 256>>>(P, AEXT);

    k_mma<<<dim3(4 * B / 128, KDIM / 128), 128, mma_smem>>>(AEXT, BEXT, Y, YH, YL, 62 * B);

    k_combine_mma<63, 2><<<dim3(2, B), 128, c2_smem>>>(A2E, YH, YL, Y, Z2);
    k_msg<<<dim3(2, B), 256>>>(AC2m, Z2, FE, S2, 2, 60, 2);
    k_l2mma<<<dim3(4, 4, 7), 128, mma_smem>>>(FE, CW1E, P, 512);
    k_l2red<<<(512 * 512 + 255) / 256, 256>>>(P, U, 512);

    k_logits<<<B, 352>>>(U, typeW, typeB, (float*)d_out);
}